// round 1
// baseline (speedup 1.0000x reference)
#include <cuda_runtime.h>
#include <cstdint>
#include <cstddef>

#define B_  2048
#define S_  65
#define SW  64
#define D_  256
#define H_  8
#define L_  256
#define HL  2048
#define SD  (S_*D_)   // 16640

// Scratch (device globals: no allocation allowed)
__device__ __align__(16) float g_A[(B_ + SW) * HL];   // preK: rows 0..2047 = origin@Wk, rows 2048..2111 = P@Wk
__device__ __align__(16) float g_res[B_ * HL];        // attention result per (b, h*L + l)

// ---------------- helpers ----------------
__device__ __forceinline__ float sigf(float x) {
    return __fdividef(1.0f, 1.0f + __expf(-x));
}
__device__ __forceinline__ unsigned long long pack2(float x, float y) {
    unsigned long long r;
    asm("mov.b64 %0, {%1, %2};" : "=l"(r) : "f"(x), "f"(y));
    return r;
}
__device__ __forceinline__ void unpack2(unsigned long long v, float& x, float& y) {
    asm("mov.b64 {%0, %1}, %2;" : "=f"(x), "=f"(y) : "l"(v));
}
__device__ __forceinline__ unsigned long long fma2(unsigned long long a, unsigned long long b,
                                                   unsigned long long c) {
    unsigned long long d;
    asm("fma.rn.f32x2 %0, %1, %2, %3;" : "=l"(d) : "l"(a), "l"(b), "l"(c));
    return d;
}
__device__ __forceinline__ void cp16(void* s, const void* g) {
    unsigned sa = (unsigned)__cvta_generic_to_shared(s);
    asm volatile("cp.async.cg.shared.global [%0], [%1], 16;\n" ::"r"(sa), "l"(g));
}
__device__ __forceinline__ void cp_commit() { asm volatile("cp.async.commit_group;\n"); }
template <int N>
__device__ __forceinline__ void cp_wait() { asm volatile("cp.async.wait_group %0;\n" ::"n"(N)); }

// ---------------- 64x256 GEMM core (K in chunks of 16, double buffered) ----------------
// Thread t: tx = t&15 -> cols {tx*4 + g*64 + e : g<4, e<4}; ty = t>>4 -> rows {ty*4+i : i<4}.
// acc2[i][g*2+hf] holds the f32x2 pair for cols (tx*4 + g*64 + hf*2, +1).
template <int NCH>
__device__ __forceinline__ void gemm64x256(const float* __restrict__ rowBase, int rowStride,
                                           const float* __restrict__ Wg,
                                           unsigned long long (&acc2)[4][8],
                                           float (&sA)[2][SW * 16], float (&sB)[2][16 * L_],
                                           int t, int tx, int ty) {
    const int ar = t >> 2;          // A row (0..63)
    const int ac = (t & 3) * 4;     // A col within chunk
    const int br = t >> 4;          // B row (0..15)
    const int bc = (t & 15) * 16;   // B col base

    // chunk loads
    {
        cp16(&sA[0][ar * 16 + ac], rowBase + (size_t)ar * rowStride + ac);
        const float* src = Wg + (size_t)br * L_ + bc;
        float* dst = &sB[0][br * L_ + bc];
        cp16(dst + 0, src + 0); cp16(dst + 4, src + 4);
        cp16(dst + 8, src + 8); cp16(dst + 12, src + 12);
        cp_commit();
    }
#pragma unroll 1
    for (int c = 0; c < NCH; ++c) {
        const int cur = c & 1;
        if (c + 1 < NCH) {
            const int nb = cur ^ 1;
            cp16(&sA[nb][ar * 16 + ac], rowBase + (size_t)ar * rowStride + (c + 1) * 16 + ac);
            const float* src = Wg + (size_t)((c + 1) * 16 + br) * L_ + bc;
            float* dst = &sB[nb][br * L_ + bc];
            cp16(dst + 0, src + 0); cp16(dst + 4, src + 4);
            cp16(dst + 8, src + 8); cp16(dst + 12, src + 12);
            cp_commit();
            cp_wait<1>();
        } else {
            cp_wait<0>();
        }
        __syncthreads();
#pragma unroll
        for (int k4 = 0; k4 < 4; ++k4) {
            float avv[4][4];
#pragma unroll
            for (int i = 0; i < 4; ++i) {
                float4 tmp = *(const float4*)&sA[cur][(ty * 4 + i) * 16 + k4 * 4];
                avv[i][0] = tmp.x; avv[i][1] = tmp.y; avv[i][2] = tmp.z; avv[i][3] = tmp.w;
            }
#pragma unroll
            for (int q = 0; q < 4; ++q) {
                unsigned long long a2[4];
#pragma unroll
                for (int i = 0; i < 4; ++i) a2[i] = pack2(avv[i][q], avv[i][q]);
                const int kk = k4 * 4 + q;
#pragma unroll
                for (int g = 0; g < 4; ++g) {
                    ulonglong2 bb = *(const ulonglong2*)&sB[cur][kk * L_ + tx * 4 + g * 64];
#pragma unroll
                    for (int i = 0; i < 4; ++i) {
                        acc2[i][g * 2 + 0] = fma2(a2[i], bb.x, acc2[i][g * 2 + 0]);
                        acc2[i][g * 2 + 1] = fma2(a2[i], bb.y, acc2[i][g * 2 + 1]);
                    }
                }
            }
        }
        __syncthreads();
    }
}

// ---------------- k1: preK = [origin ; P] @ Wk (raw preactivation) ----------------
__global__ void __launch_bounds__(256, 2)
k1_preK(const float* __restrict__ x, const float* __restrict__ Wk, const float* __restrict__ P) {
    __shared__ __align__(16) float sA[2][SW * 16];
    __shared__ __align__(16) float sB[2][16 * L_];
    const int h = blockIdx.x, mt = blockIdx.y;  // mt: 0..32 (32 origin tiles + 1 P tile)
    const int t = threadIdx.x, tx = t & 15, ty = t >> 4;

    const float* base;
    int stride;
    if (mt < 32) { base = x + (size_t)mt * 64 * SD; stride = SD; }  // origin rows: x[b,0,:]
    else         { base = P; stride = D_; }

    unsigned long long acc2[4][8];
#pragma unroll
    for (int i = 0; i < 4; ++i)
#pragma unroll
        for (int p = 0; p < 8; ++p) acc2[i][p] = 0ull;

    gemm64x256<16>(base, stride, Wk + h * (D_ * L_), acc2, sA, sB, t, tx, ty);

#pragma unroll
    for (int i = 0; i < 4; ++i) {
        const size_t row = (size_t)mt * 64 + ty * 4 + i;
        float* dst = g_A + row * HL + h * L_ + tx * 4;
#pragma unroll
        for (int g = 0; g < 4; ++g)
#pragma unroll
            for (int hf = 0; hf < 2; ++hf) {
                float f0, f1;
                unpack2(acc2[i][g * 2 + hf], f0, f1);
                dst[g * 64 + hf * 2 + 0] = f0;
                dst[g * 64 + hf * 2 + 1] = f1;
            }
    }
}

// ---------------- k2: fused q/k/score/softmax/v/res, one block per (h, b) ----------------
__global__ void __launch_bounds__(256, 2)
k2_main(const float* __restrict__ x, const float* __restrict__ Wq,
        const float* __restrict__ Wv, const float* __restrict__ Wsc) {
    __shared__ __align__(16) float sA[2][SW * 16];
    __shared__ __align__(16) float sB[2][16 * L_];
    __shared__ float sSc[SW];
    __shared__ float sWgt[SW + 1];
    const int h = blockIdx.x, b = blockIdx.y;
    const int t = threadIdx.x, tx = t & 15, ty = t >> 4;
    const float* walk = x + (size_t)b * SD + D_;  // x[b, 1:, :]

    unsigned long long acc2[4][8];
#pragma unroll
    for (int i = 0; i < 4; ++i)
#pragma unroll
        for (int p = 0; p < 8; ++p) acc2[i][p] = 0ull;

    // ---- q preactivation GEMM ----
    gemm64x256<16>(walk, D_, Wq + h * (D_ * L_), acc2, sA, sB, t, tx, ty);

    // ---- q epilogue: score partials (scorePart aliases sB[0], GEMM is done+synced) ----
    float* scorePart = &sB[0][0];  // [64][16]
    {
        const float* pA = g_A + (size_t)b * HL + h * L_ + tx * 4;
        const float* pW = Wsc + h * L_ + tx * 4;
        float ka[16], wv[16];
#pragma unroll
        for (int g = 0; g < 4; ++g) {
            float4 kk4 = *(const float4*)(pA + g * 64);
            float4 ww4 = *(const float4*)(pW + g * 64);
            ka[g * 4 + 0] = kk4.x; ka[g * 4 + 1] = kk4.y; ka[g * 4 + 2] = kk4.z; ka[g * 4 + 3] = kk4.w;
            wv[g * 4 + 0] = ww4.x; wv[g * 4 + 1] = ww4.y; wv[g * 4 + 2] = ww4.z; wv[g * 4 + 3] = ww4.w;
        }
#pragma unroll
        for (int i = 0; i < 4; ++i) {
            const int s = ty * 4 + i;
            const float* pPK = g_A + (size_t)(B_ + s) * HL + h * L_ + tx * 4;
            float ps = 0.f;
#pragma unroll
            for (int g = 0; g < 4; ++g) {
                float4 pk4 = *(const float4*)(pPK + g * 64);
                float pkv[4] = {pk4.x, pk4.y, pk4.z, pk4.w};
#pragma unroll
                for (int hf = 0; hf < 2; ++hf) {
                    float f0, f1;
                    unpack2(acc2[i][g * 2 + hf], f0, f1);
                    const int c0 = g * 4 + hf * 2;
                    const float qa = sigf(f0);
                    const float qb = sigf(f1);
                    const float k0 = sigf(ka[c0 + 0] + pkv[hf * 2 + 0]);
                    const float k1 = sigf(ka[c0 + 1] + pkv[hf * 2 + 1]);
                    ps += __cosf(qa * k0) * wv[c0] + __cosf(qb * k1) * wv[c0 + 1];
                }
            }
            scorePart[s * 16 + tx] = ps;
        }
    }
    __syncthreads();
    if (t < SW) {
        float sc = 0.f;
#pragma unroll
        for (int j = 0; j < 16; ++j) sc += scorePart[t * 16 + j];
        sSc[t] = sc;
    }
    __syncthreads();
    if (t < 32) {
        float v0 = sSc[t], v1 = sSc[t + 32];
        float m = fmaxf(v0, v1);
#pragma unroll
        for (int o = 16; o > 0; o >>= 1) m = fmaxf(m, __shfl_xor_sync(0xffffffffu, m, o));
        float e0 = __expf(v0 - m), e1 = __expf(v1 - m);
        float sm = e0 + e1;
#pragma unroll
        for (int o = 16; o > 0; o >>= 1) sm += __shfl_xor_sync(0xffffffffu, sm, o);
        sWgt[t] = e0;
        sWgt[t + 32] = e1;
        if (t == 0) sWgt[SW] = __fdividef(1.f, sm);
    }
    __syncthreads();

    // ---- v preactivation GEMM ----
#pragma unroll
    for (int i = 0; i < 4; ++i)
#pragma unroll
        for (int p = 0; p < 8; ++p) acc2[i][p] = 0ull;
    gemm64x256<16>(walk, D_, Wv + h * (D_ * L_), acc2, sA, sB, t, tx, ty);

    // ---- v epilogue: weighted partial sums (resPart aliases sB[0]) ----
    float* resPart = &sB[0][0];  // [16][256]
    {
        float r[16];
#pragma unroll
        for (int c = 0; c < 16; ++c) r[c] = 0.f;
#pragma unroll
        for (int i = 0; i < 4; ++i) {
            const float wi = sWgt[ty * 4 + i];
#pragma unroll
            for (int g = 0; g < 4; ++g)
#pragma unroll
                for (int hf = 0; hf < 2; ++hf) {
                    float f0, f1;
                    unpack2(acc2[i][g * 2 + hf], f0, f1);
                    r[g * 4 + hf * 2 + 0] += wi * sigf(f0);
                    r[g * 4 + hf * 2 + 1] += wi * sigf(f1);
                }
        }
#pragma unroll
        for (int g = 0; g < 4; ++g)
#pragma unroll
            for (int c = 0; c < 4; ++c)
                resPart[ty * L_ + tx * 4 + g * 64 + c] = r[g * 4 + c];
    }
    __syncthreads();
    {
        float acc = 0.f;
#pragma unroll
        for (int j = 0; j < 16; ++j) acc += resPart[j * L_ + t];
        g_res[(size_t)b * HL + h * L_ + t] = acc * sWgt[SW];
    }
}

// ---------------- k3: out[:, :256] = sigmoid(res @ O) ----------------
__global__ void __launch_bounds__(256, 2)
k3_out(const float* __restrict__ O, float* __restrict__ out) {
    __shared__ __align__(16) float sA[2][SW * 16];
    __shared__ __align__(16) float sB[2][16 * 64];
    const int ct = blockIdx.x;  // 0..3  (d-tile of 64)
    const int bt = blockIdx.y;  // 0..31 (b-tile of 64)
    const int t = threadIdx.x, tx = t & 15, ty = t >> 4;
    const int ar = t >> 2, ac = (t & 3) * 4;
    const int br = t >> 4, bc = (t & 15) * 4;

    const float* rowBase = g_res + (size_t)bt * 64 * HL;

    unsigned long long acc2[4][2];
#pragma unroll
    for (int i = 0; i < 4; ++i) { acc2[i][0] = 0ull; acc2[i][1] = 0ull; }

    cp16(&sA[0][ar * 16 + ac], rowBase + (size_t)ar * HL + ac);
    cp16(&sB[0][br * 64 + bc], O + (size_t)br * D_ + ct * 64 + bc);
    cp_commit();
#pragma unroll 1
    for (int c = 0; c < 128; ++c) {
        const int cur = c & 1;
        if (c + 1 < 128) {
            const int nb = cur ^ 1;
            cp16(&sA[nb][ar * 16 + ac], rowBase + (size_t)ar * HL + (c + 1) * 16 + ac);
            cp16(&sB[nb][br * 64 + bc], O + (size_t)((c + 1) * 16 + br) * D_ + ct * 64 + bc);
            cp_commit();
            cp_wait<1>();
        } else {
            cp_wait<0>();
        }
        __syncthreads();
#pragma unroll
        for (int k4 = 0; k4 < 4; ++k4) {
            float avv[4][4];
#pragma unroll
            for (int i = 0; i < 4; ++i) {
                float4 tmp = *(const float4*)&sA[cur][(ty * 4 + i) * 16 + k4 * 4];
                avv[i][0] = tmp.x; avv[i][1] = tmp.y; avv[i][2] = tmp.z; avv[i][3] = tmp.w;
            }
#pragma unroll
            for (int q = 0; q < 4; ++q) {
                const int kk = k4 * 4 + q;
                ulonglong2 bb = *(const ulonglong2*)&sB[cur][kk * 64 + tx * 4];
#pragma unroll
                for (int i = 0; i < 4; ++i) {
                    unsigned long long a2 = pack2(avv[i][q], avv[i][q]);
                    acc2[i][0] = fma2(a2, bb.x, acc2[i][0]);
                    acc2[i][1] = fma2(a2, bb.y, acc2[i][1]);
                }
            }
        }
        __syncthreads();
    }
#pragma unroll
    for (int i = 0; i < 4; ++i) {
        const size_t bb = (size_t)bt * 64 + ty * 4 + i;
#pragma unroll
        for (int hf = 0; hf < 2; ++hf) {
            float f0, f1;
            unpack2(acc2[i][hf], f0, f1);
            const int d = ct * 64 + tx * 4 + hf * 2;
            out[bb * 512 + d + 0] = sigf(f0);
            out[bb * 512 + d + 1] = sigf(f1);
        }
    }
}

// ---------------- k4: out[:, 256:512] = origin ----------------
__global__ void k4_copy(const float* __restrict__ x, float* __restrict__ out) {
    const int idx = blockIdx.x * 256 + threadIdx.x;  // one float4 each
    const int b = idx >> 6;
    const int d4 = (idx & 63) * 4;
    float4 v = *(const float4*)(x + (size_t)b * SD + d4);
    *(float4*)(out + (size_t)b * 512 + 256 + d4) = v;
}

// ---------------- launch ----------------
extern "C" void kernel_launch(void* const* d_in, const int* in_sizes, int n_in,
                              void* d_out, int out_size) {
    const float* x  = (const float*)d_in[0];
    const float* Wq = (const float*)d_in[1];
    const float* Wk = (const float*)d_in[2];
    const float* Wv = (const float*)d_in[3];
    const float* W  = (const float*)d_in[4];
    const float* O  = (const float*)d_in[5];
    const float* P  = (const float*)d_in[6];
    // d_in[7] = bias: provably cancels under softmax (constant shift per (b,h)); unused.
    float* out = (float*)d_out;

    k1_preK<<<dim3(H_, 33), 256>>>(x, Wk, P);
    k2_main<<<dim3(H_, B_), 256>>>(x, Wq, Wv, W);
    k3_out<<<dim3(4, 32), 256>>>(O, out);
    k4_copy<<<512, 256>>>(x, out);
}